// round 15
// baseline (speedup 1.0000x reference)
#include <cuda_runtime.h>
#include <cstddef>

// Grefenstette stack forward, closed-form reformulation.
//
//   s_t[j] = relu(d_j - relu(M_{j,t} - H_j)),  M_{j,t} = max_{j<tau<=t} G_tau
//     G_tau = P_tau - D_{tau-1},  H_j = P_j - D_j,  P = cumsum(u), D = cumsum(d)
//   w_t[j] = min(1, R_t[j]) - min(1, R_t[j+1]),  R = suffix-sum of s_t
//   out[t,b,:] = sum_j w_t[j] * v[j,b,:]
//
// K1: fp64 shuffle-scan prefix sums (block per batch) -> packed GHD [B][T].
// K2: fused weights+gather, warp per (t,b). Top row prefetched behind the
//     GHD load; residual rows drained with a depth-2 software pipeline
//     (next row's loads issued before current row's FMA).

#define TT 512
#define BB 128
#define EE 256

#define FULL 0xFFFFFFFFu
#define GW 8      // gather warps per block

__device__ float4 g_S[BB][TT];   // (G, H, D, pad)

// ---------------------------------------------------------------------------
// Kernel 1: fp64 prefix sums (shuffle scan, 2 syncs). One block per batch.
// ---------------------------------------------------------------------------
__global__ __launch_bounds__(TT) void scan_kernel(const float* __restrict__ u,
                                                  const float* __restrict__ d) {
    __shared__ double wsU[16];
    __shared__ double wsD[16];

    const int b    = blockIdx.x;
    const int t    = threadIdx.x;
    const int wid  = t >> 5;
    const int lane = t & 31;

    const float uv = __ldg(&u[t * BB + b]);
    const float dv = __ldg(&d[t * BB + b]);

    double xu = (double)uv;
    double xd = (double)dv;
    #pragma unroll
    for (int o = 1; o < 32; o <<= 1) {
        const double yu = __shfl_up_sync(FULL, xu, o);
        const double yd = __shfl_up_sync(FULL, xd, o);
        if (lane >= o) { xu += yu; xd += yd; }
    }
    if (lane == 31) { wsU[wid] = xu; wsD[wid] = xd; }
    __syncthreads();
    if (wid == 0) {
        double tu = (lane < 16) ? wsU[lane] : 0.0;
        double td = (lane < 16) ? wsD[lane] : 0.0;
        #pragma unroll
        for (int o = 1; o < 16; o <<= 1) {
            const double yu = __shfl_up_sync(FULL, tu, o);
            const double yd = __shfl_up_sync(FULL, td, o);
            if (lane >= o) { tu += yu; td += yd; }
        }
        if (lane < 16) { wsU[lane] = tu; wsD[lane] = td; }
    }
    __syncthreads();
    const double offU = (wid > 0) ? wsU[wid - 1] : 0.0;
    const double offD = (wid > 0) ? wsD[wid - 1] : 0.0;

    const double P  = xu + offU;
    const double Dc = xd + offD;

    g_S[b][t] = make_float4((float)(P - (Dc - (double)dv)),  // G
                            (float)(P - Dc),                 // H
                            dv, 0.f);                        // D
}

// ---------------------------------------------------------------------------
// Kernel 2: fused weights + gather. Warp per (t,b); grid (TT/GW, BB).
// ---------------------------------------------------------------------------
__global__ __launch_bounds__(GW * 32, 6) void gather_kernel(
    const float* __restrict__ v, float* __restrict__ out) {
    const int tid  = threadIdx.x;
    const int warp = tid >> 5;
    const int lane = tid & 31;
    const int t    = blockIdx.x * GW + warp;
    const int b    = blockIdx.y;

    const float4* __restrict__ v4 = reinterpret_cast<const float4*>(v);
    float4* __restrict__ o4       = reinterpret_cast<float4*>(out);

    // ---- Scan-chain head: one packed LDG.128 (issued FIRST) ----
    const int  j  = t - lane;
    const bool ok = (j >= 0);
    const float4 ghd = ok ? __ldg(&g_S[b][j])
                          : make_float4(-1e30f, 0.f, 0.f, 0.f);

    // ---- Prefetch the always-contributing top row (behind ghd in queue) ----
    const float4* vt = v4 + ((size_t)t * BB + b) * (EE / 4);
    const float4 p0 = __ldg(vt + lane);
    const float4 p1 = __ldg(vt + lane + 32);

    // ---- First chunk: warp scan over slots t-31..t ----
    float m        = ghd.x;
    const float Hj = ghd.y;
    const float Dj = ghd.z;

    // Inclusive forward max-scan of G over lanes (lane 0 = slot t).
    #pragma unroll
    for (int o = 1; o < 32; o <<= 1) {
        const float x = __shfl_up_sync(FULL, m, o);
        if (lane >= o) m = fmaxf(m, x);
    }
    float Me = __shfl_up_sync(FULL, m, 1);
    if (lane == 0) Me = -1e30f;

    const float s = ok ? fmaxf(Dj - fmaxf(Me - Hj, 0.f), 0.f) : 0.f;

    // Inclusive forward sum-scan of s over lanes.
    float a = s;
    #pragma unroll
    for (int o = 1; o < 32; o <<= 1) {
        const float x = __shfl_up_sync(FULL, a, o);
        if (lane >= o) a += x;
    }
    const float accExc = a - s;
    const float w0 = fminf(a, 1.f) - fminf(accExc, 1.f);

    // ---- Top row FMA from the prefetch (weight = lane 0's w0) ----
    const float wtop = __shfl_sync(FULL, w0, 0);

    float4 r0, r1;
    r0.x = wtop * p0.x;  r0.y = wtop * p0.y;
    r0.z = wtop * p0.z;  r0.w = wtop * p0.w;
    r1.x = wtop * p1.x;  r1.y = wtop * p1.y;
    r1.z = wtop * p1.z;  r1.w = wtop * p1.w;

    // ---- Residual rows: depth-2 software pipeline ----
    unsigned mask = __ballot_sync(FULL, w0 > 0.f) & ~1u;
    {
        bool   have = (mask != 0u);
        float  wc = 0.f;
        float4 a0, a1;
        if (have) {
            const int src = __ffs(mask) - 1;
            mask &= mask - 1;
            wc = __shfl_sync(FULL, w0, src);
            const float4* vp = v4 + ((size_t)(t - src) * BB + b) * (EE / 4);
            a0 = __ldg(vp + lane);
            a1 = __ldg(vp + lane + 32);
        }
        while (have) {
            bool   haveN = (mask != 0u);
            float  wn = 0.f;
            float4 b0, b1;
            if (haveN) {
                const int src = __ffs(mask) - 1;
                mask &= mask - 1;
                wn = __shfl_sync(FULL, w0, src);
                const float4* vp = v4 + ((size_t)(t - src) * BB + b) * (EE / 4);
                b0 = __ldg(vp + lane);          // issued before FMA/wait on a0
                b1 = __ldg(vp + lane + 32);
            }
            r0.x = fmaf(wc, a0.x, r0.x);
            r0.y = fmaf(wc, a0.y, r0.y);
            r0.z = fmaf(wc, a0.z, r0.z);
            r0.w = fmaf(wc, a0.w, r0.w);
            r1.x = fmaf(wc, a1.x, r1.x);
            r1.y = fmaf(wc, a1.y, r1.y);
            r1.z = fmaf(wc, a1.z, r1.z);
            r1.w = fmaf(wc, a1.w, r1.w);
            have = haveN;
            wc = wn;
            a0 = b0;
            a1 = b1;
        }
    }

    // ---- Rare continuation: deeper chunks (exact warp-scan loop) ----
    float carryAcc = __shfl_sync(FULL, a, 31);
    if (carryAcc < 1.f && t >= 32) {
        float carryM = __shfl_sync(FULL, m, 31);
        for (int jtop = t - 32; jtop >= 0 && carryAcc < 1.f; jtop -= 32) {
            const int  jc  = jtop - lane;
            const bool okc = (jc >= 0);
            const float4 gc = okc ? __ldg(&g_S[b][jc])
                                  : make_float4(-1e30f, 0.f, 0.f, 0.f);

            float mc = gc.x;
            #pragma unroll
            for (int o = 1; o < 32; o <<= 1) {
                const float x = __shfl_up_sync(FULL, mc, o);
                if (lane >= o) mc = fmaxf(mc, x);
            }
            float Mec = __shfl_up_sync(FULL, mc, 1);
            if (lane == 0) Mec = -1e30f;
            Mec = fmaxf(Mec, carryM);

            const float sc = okc ? fmaxf(gc.z - fmaxf(Mec - gc.y, 0.f), 0.f) : 0.f;

            float ac = sc;
            #pragma unroll
            for (int o = 1; o < 32; o <<= 1) {
                const float x = __shfl_up_sync(FULL, ac, o);
                if (lane >= o) ac += x;
            }
            const float accInc = carryAcc + ac;
            const float accEx2 = accInc - sc;
            const float wcn = fminf(accInc, 1.f) - fminf(accEx2, 1.f);

            unsigned m2 = __ballot_sync(FULL, wcn > 0.f);
            while (m2) {
                const int src = __ffs(m2) - 1;
                m2 &= m2 - 1;
                const float wj = __shfl_sync(FULL, wcn, src);
                const int   jj = jtop - src;
                const float4* vp = v4 + ((size_t)jj * BB + b) * (EE / 4);
                const float4 b0 = __ldg(vp + lane);
                const float4 b1 = __ldg(vp + lane + 32);
                r0.x = fmaf(wj, b0.x, r0.x);
                r0.y = fmaf(wj, b0.y, r0.y);
                r0.z = fmaf(wj, b0.z, r0.z);
                r0.w = fmaf(wj, b0.w, r0.w);
                r1.x = fmaf(wj, b1.x, r1.x);
                r1.y = fmaf(wj, b1.y, r1.y);
                r1.z = fmaf(wj, b1.z, r1.z);
                r1.w = fmaf(wj, b1.w, r1.w);
            }

            carryAcc = __shfl_sync(FULL, accInc, 31);
            carryM   = fmaxf(carryM, __shfl_sync(FULL, mc, 31));
        }
    }

    float4* op = o4 + ((size_t)t * BB + b) * (EE / 4);
    op[lane]      = r0;
    op[lane + 32] = r1;
}

extern "C" void kernel_launch(void* const* d_in, const int* in_sizes, int n_in,
                              void* d_out, int out_size) {
    const float* v = (const float*)d_in[0];  // [T,B,E]
    const float* u = (const float*)d_in[1];  // [T,B]
    const float* d = (const float*)d_in[2];  // [T,B]
    float* out     = (float*)d_out;          // [T,B,E]

    scan_kernel<<<BB, TT>>>(u, d);

    dim3 ggrid(TT / GW, BB);
    gather_kernel<<<ggrid, GW * 32>>>(v, out);
}

// round 17
// speedup vs baseline: 1.1425x; 1.1425x over previous
#include <cuda_runtime.h>
#include <cstddef>

// Grefenstette stack forward, closed-form reformulation.
//
//   s_t[j] = relu(d_j - relu(M_{j,t} - H_j)),  M_{j,t} = max_{j<tau<=t} G_tau
//     G_tau = P_tau - D_{tau-1},  H_j = P_j - D_j,  P = cumsum(u), D = cumsum(d)
//   w_t[j] = min(1, R_t[j]) - min(1, R_t[j+1]),  R = suffix-sum of s_t
//   out[t,b,:] = sum_j w_t[j] * v[j,b,:]
//
// K1: fp64 shuffle-scan prefix sums (block per batch) -> packed GHD [B][T].
// K2: fused weights+gather, warp per (t,b), 128-thread blocks (fine-grain
//     scheduling, less CTA tail). Top row prefetched behind the GHD load.

#define TT 512
#define BB 128
#define EE 256

#define FULL 0xFFFFFFFFu
#define GW 4      // gather warps per block (128 threads)

__device__ float4 g_S[BB][TT];   // (G, H, D, pad)

// ---------------------------------------------------------------------------
// Kernel 1: fp64 prefix sums (shuffle scan, 2 syncs). One block per batch.
// ---------------------------------------------------------------------------
__global__ __launch_bounds__(TT) void scan_kernel(const float* __restrict__ u,
                                                  const float* __restrict__ d) {
    __shared__ double wsU[16];
    __shared__ double wsD[16];

    const int b    = blockIdx.x;
    const int t    = threadIdx.x;
    const int wid  = t >> 5;
    const int lane = t & 31;

    const float uv = __ldg(&u[t * BB + b]);
    const float dv = __ldg(&d[t * BB + b]);

    double xu = (double)uv;
    double xd = (double)dv;
    #pragma unroll
    for (int o = 1; o < 32; o <<= 1) {
        const double yu = __shfl_up_sync(FULL, xu, o);
        const double yd = __shfl_up_sync(FULL, xd, o);
        if (lane >= o) { xu += yu; xd += yd; }
    }
    if (lane == 31) { wsU[wid] = xu; wsD[wid] = xd; }
    __syncthreads();
    if (wid == 0) {
        double tu = (lane < 16) ? wsU[lane] : 0.0;
        double td = (lane < 16) ? wsD[lane] : 0.0;
        #pragma unroll
        for (int o = 1; o < 16; o <<= 1) {
            const double yu = __shfl_up_sync(FULL, tu, o);
            const double yd = __shfl_up_sync(FULL, td, o);
            if (lane >= o) { tu += yu; td += yd; }
        }
        if (lane < 16) { wsU[lane] = tu; wsD[lane] = td; }
    }
    __syncthreads();
    const double offU = (wid > 0) ? wsU[wid - 1] : 0.0;
    const double offD = (wid > 0) ? wsD[wid - 1] : 0.0;

    const double P  = xu + offU;
    const double Dc = xd + offD;

    g_S[b][t] = make_float4((float)(P - (Dc - (double)dv)),  // G
                            (float)(P - Dc),                 // H
                            dv, 0.f);                        // D
}

// ---------------------------------------------------------------------------
// Kernel 2: fused weights + gather. Warp per (t,b); grid (TT/GW, BB).
// ---------------------------------------------------------------------------
__global__ __launch_bounds__(GW * 32, 16) void gather_kernel(
    const float* __restrict__ v, float* __restrict__ out) {
    const int tid  = threadIdx.x;
    const int warp = tid >> 5;
    const int lane = tid & 31;
    const int t    = blockIdx.x * GW + warp;
    const int b    = blockIdx.y;

    const float4* __restrict__ v4 = reinterpret_cast<const float4*>(v);
    float4* __restrict__ o4       = reinterpret_cast<float4*>(out);

    // ---- Scan-chain head: one packed LDG.128 (issued FIRST) ----
    const int  j  = t - lane;
    const bool ok = (j >= 0);
    const float4 ghd = ok ? __ldg(&g_S[b][j])
                          : make_float4(-1e30f, 0.f, 0.f, 0.f);

    // ---- Prefetch the always-contributing top row (behind ghd in queue) ----
    const float4* vt = v4 + ((size_t)t * BB + b) * (EE / 4);
    const float4 p0 = __ldg(vt + lane);
    const float4 p1 = __ldg(vt + lane + 32);

    // ---- First chunk: warp scan over slots t-31..t ----
    float m        = ghd.x;
    const float Hj = ghd.y;
    const float Dj = ghd.z;

    // Inclusive forward max-scan of G over lanes (lane 0 = slot t).
    #pragma unroll
    for (int o = 1; o < 32; o <<= 1) {
        const float x = __shfl_up_sync(FULL, m, o);
        if (lane >= o) m = fmaxf(m, x);
    }
    float Me = __shfl_up_sync(FULL, m, 1);
    if (lane == 0) Me = -1e30f;

    const float s = ok ? fmaxf(Dj - fmaxf(Me - Hj, 0.f), 0.f) : 0.f;

    // Inclusive forward sum-scan of s over lanes.
    float a = s;
    #pragma unroll
    for (int o = 1; o < 32; o <<= 1) {
        const float x = __shfl_up_sync(FULL, a, o);
        if (lane >= o) a += x;
    }
    const float accExc = a - s;
    const float w0 = fminf(a, 1.f) - fminf(accExc, 1.f);

    // ---- Top row FMA from the prefetch (weight = lane 0's w0) ----
    const float wtop = __shfl_sync(FULL, w0, 0);

    float4 r0, r1;
    r0.x = wtop * p0.x;  r0.y = wtop * p0.y;
    r0.z = wtop * p0.z;  r0.w = wtop * p0.w;
    r1.x = wtop * p1.x;  r1.y = wtop * p1.y;
    r1.z = wtop * p1.z;  r1.w = wtop * p1.w;

    // ---- Remaining rows (skip bit 0 = top slot) ----
    unsigned mask = __ballot_sync(FULL, w0 > 0.f) & ~1u;
    while (mask) {
        const int src = __ffs(mask) - 1;
        mask &= mask - 1;
        const float wj = __shfl_sync(FULL, w0, src);
        const int   jj = t - src;
        const float4* vp = v4 + ((size_t)jj * BB + b) * (EE / 4);
        const float4 a0 = __ldg(vp + lane);
        const float4 a1 = __ldg(vp + lane + 32);
        r0.x = fmaf(wj, a0.x, r0.x);
        r0.y = fmaf(wj, a0.y, r0.y);
        r0.z = fmaf(wj, a0.z, r0.z);
        r0.w = fmaf(wj, a0.w, r0.w);
        r1.x = fmaf(wj, a1.x, r1.x);
        r1.y = fmaf(wj, a1.y, r1.y);
        r1.z = fmaf(wj, a1.z, r1.z);
        r1.w = fmaf(wj, a1.w, r1.w);
    }

    // ---- Rare continuation: deeper chunks (exact warp-scan loop) ----
    float carryAcc = __shfl_sync(FULL, a, 31);
    if (carryAcc < 1.f && t >= 32) {
        float carryM = __shfl_sync(FULL, m, 31);
        for (int jtop = t - 32; jtop >= 0 && carryAcc < 1.f; jtop -= 32) {
            const int  jc  = jtop - lane;
            const bool okc = (jc >= 0);
            const float4 gc = okc ? __ldg(&g_S[b][jc])
                                  : make_float4(-1e30f, 0.f, 0.f, 0.f);

            float mc = gc.x;
            #pragma unroll
            for (int o = 1; o < 32; o <<= 1) {
                const float x = __shfl_up_sync(FULL, mc, o);
                if (lane >= o) mc = fmaxf(mc, x);
            }
            float Mec = __shfl_up_sync(FULL, mc, 1);
            if (lane == 0) Mec = -1e30f;
            Mec = fmaxf(Mec, carryM);

            const float sc = okc ? fmaxf(gc.z - fmaxf(Mec - gc.y, 0.f), 0.f) : 0.f;

            float ac = sc;
            #pragma unroll
            for (int o = 1; o < 32; o <<= 1) {
                const float x = __shfl_up_sync(FULL, ac, o);
                if (lane >= o) ac += x;
            }
            const float accInc = carryAcc + ac;
            const float accEx2 = accInc - sc;
            const float wc = fminf(accInc, 1.f) - fminf(accEx2, 1.f);

            unsigned m2 = __ballot_sync(FULL, wc > 0.f);
            while (m2) {
                const int src = __ffs(m2) - 1;
                m2 &= m2 - 1;
                const float wj = __shfl_sync(FULL, wc, src);
                const int   jj = jtop - src;
                const float4* vp = v4 + ((size_t)jj * BB + b) * (EE / 4);
                const float4 b0 = __ldg(vp + lane);
                const float4 b1 = __ldg(vp + lane + 32);
                r0.x = fmaf(wj, b0.x, r0.x);
                r0.y = fmaf(wj, b0.y, r0.y);
                r0.z = fmaf(wj, b0.z, r0.z);
                r0.w = fmaf(wj, b0.w, r0.w);
                r1.x = fmaf(wj, b1.x, r1.x);
                r1.y = fmaf(wj, b1.y, r1.y);
                r1.z = fmaf(wj, b1.z, r1.z);
                r1.w = fmaf(wj, b1.w, r1.w);
            }

            carryAcc = __shfl_sync(FULL, accInc, 31);
            carryM   = fmaxf(carryM, __shfl_sync(FULL, mc, 31));
        }
    }

    float4* op = o4 + ((size_t)t * BB + b) * (EE / 4);
    op[lane]      = r0;
    op[lane + 32] = r1;
}

extern "C" void kernel_launch(void* const* d_in, const int* in_sizes, int n_in,
                              void* d_out, int out_size) {
    const float* v = (const float*)d_in[0];  // [T,B,E]
    const float* u = (const float*)d_in[1];  // [T,B]
    const float* d = (const float*)d_in[2];  // [T,B]
    float* out     = (float*)d_out;          // [T,B,E]

    scan_kernel<<<BB, TT>>>(u, d);

    dim3 ggrid(TT / GW, BB);
    gather_kernel<<<ggrid, GW * 32>>>(v, out);
}